// round 1
// baseline (speedup 1.0000x reference)
#include <cuda_runtime.h>
#include <cuda_bf16.h>

// Fused gamma-pdf-weighted MSE mean reduction.
// mean( 0.5*(output-target)^2 * ef(target) )
// ef(y) = (BETA - c)*(1 - pdf(y)/FX_MAX) + c,  c = 1/(Y_MAX - Y_MIN)
// pdf(y) = gamma.pdf(y; a, loc, scale)
//
// pdf/FX_MAX = exp( (a-1)*ln(x) - x + C0 ),  x = (y - loc)/scale
// C0 = -lgamma(a) - ln(scale) - ln(FX_MAX)
//
// For fp32 uniform targets, pdf/FX_MAX < 4e-19 for every value except exact
// zeros (where it is ~1). We compute it only when y < 1e-6 (cold branch) so
// the hot loop has no MUFU (log/exp) instructions and stays HBM-bound.

#define NBLK 1184   // 148 SMs * 8
#define NTH  256

__device__ float g_part[NBLK];

__device__ __forceinline__ float elem_val(float o, float y) {
    // Constants (compile-time doubles folded to float)
    const float A1        = -0.9355570857535674f;            // EST_A - 1
    const float NEG_LOC   = 1.1328205299926424e-27f;         // -EST_LOC
    const float INV_SCALE = (float)(1.0 / 1.5376362609160314);
    const float C0        = -58.4492351f;                    // -lgamma(a)-ln(scale)-ln(FX_MAX)
    const float C         = (float)(1.0 / 107.2185);         // 1/(Y_MAX - Y_MIN)
    const float BC        = 5.0f - (float)(1.0 / 107.2185);  // BETA - c

    float r = 0.0f;
    if (y < 1e-6f) {                      // cold path: only exact/near-zero targets
        float x  = (y + NEG_LOC) * INV_SCALE;
        float lp = fmaf(A1, __logf(x), C0) - x;
        r = __expf(lp);                   // = pdf/FX_MAX
    }
    float ef   = fmaf(BC, 1.0f - r, C);   // (BETA-c)*(1-r) + c
    float diff = o - y;
    return 0.5f * diff * diff * ef;
}

__global__ __launch_bounds__(NTH) void loss_partial_kernel(
    const float* __restrict__ out, const float* __restrict__ tgt, int n)
{
    const int tid    = threadIdx.x;
    const int idx    = blockIdx.x * NTH + tid;
    const int stride = gridDim.x * NTH;
    const int n4     = n >> 2;

    const float4* o4 = (const float4*)out;
    const float4* t4 = (const float4*)tgt;

    float sum = 0.0f;
    for (int i = idx; i < n4; i += stride) {
        float4 o = o4[i];
        float4 t = t4[i];
        sum += elem_val(o.x, t.x);
        sum += elem_val(o.y, t.y);
        sum += elem_val(o.z, t.z);
        sum += elem_val(o.w, t.w);
    }
    // tail (n not multiple of 4)
    for (int i = (n4 << 2) + idx; i < n; i += stride) {
        sum += elem_val(out[i], tgt[i]);
    }

    // warp reduce
    #pragma unroll
    for (int off = 16; off > 0; off >>= 1)
        sum += __shfl_down_sync(0xFFFFFFFFu, sum, off);

    __shared__ float s_warp[NTH / 32];
    if ((tid & 31) == 0) s_warp[tid >> 5] = sum;
    __syncthreads();

    if (tid < NTH / 32) {
        float v = s_warp[tid];
        #pragma unroll
        for (int off = (NTH / 32) / 2; off > 0; off >>= 1)
            v += __shfl_down_sync(0xFFFFFFFFu, v, off);
        if (tid == 0) g_part[blockIdx.x] = v;
    }
}

__global__ __launch_bounds__(1024) void loss_finalize_kernel(float* out, int n)
{
    const int tid = threadIdx.x;
    double sum = 0.0;
    for (int i = tid; i < NBLK; i += 1024)
        sum += (double)g_part[i];

    #pragma unroll
    for (int off = 16; off > 0; off >>= 1)
        sum += __shfl_down_sync(0xFFFFFFFFu, sum, off);

    __shared__ double s_warp[32];
    if ((tid & 31) == 0) s_warp[tid >> 5] = sum;
    __syncthreads();

    if (tid < 32) {
        double v = s_warp[tid];
        #pragma unroll
        for (int off = 16; off > 0; off >>= 1)
            v += __shfl_down_sync(0xFFFFFFFFu, v, off);
        if (tid == 0) out[0] = (float)(v / (double)n);
    }
}

extern "C" void kernel_launch(void* const* d_in, const int* in_sizes, int n_in,
                              void* d_out, int out_size)
{
    const float* output = (const float*)d_in[0];
    const float* target = (const float*)d_in[1];
    const int n = in_sizes[0];

    loss_partial_kernel<<<NBLK, NTH>>>(output, target, n);
    loss_finalize_kernel<<<1, 1024>>>((float*)d_out, n);
}